// round 12
// baseline (speedup 1.0000x reference)
#include <cuda_runtime.h>
#include <cuda_fp16.h>
#include <cstdint>

#define BATCHN 4
#define SEQ 2048
#define DM 1024
#define QL 3072            // merged QKV row stride
#define NH 16
#define HD 64
#define DFF 4096
#define MFEAT 532
#define MP 576             // padded feature dim
#define NROWS (BATCHN*SEQ) // 8192
#define NBH (BATCHN*NH)    // 64
#define KVR 128            // kvs^T rows: 64 dims + 1 sum + 63 pad
#define NXT 5              // feature GEMM x-tiles

#define DN 0.35355339059327373f          /* 64^-0.25 */
#define RATIO 0.0433555f                 /* 1/sqrt(532) */
#define FEPS 1e-6f

// ----------------- scratch (device globals; no allocation) -----------------
__device__ __half g_xnh [(size_t)NROWS*DM];
__device__ __half g_qkvh[(size_t)NROWS*QL];
__device__ __half g_qph [(size_t)NBH*SEQ*MP];
__device__ __half g_kph [(size_t)NBH*SEQ*MP];
__device__ float  g_pmaxq[(size_t)NBH*NXT*SEQ];
__device__ float  g_pmaxk[(size_t)NBH*NXT*SEQ];
__device__ float  g_stab[(size_t)BATCHN*SEQ];
__device__ __half g_kvsTh[(size_t)NBH*KVR*MP];
__device__ __half g_attnh[(size_t)NROWS*DM];
__device__ float  g_x1 [(size_t)NROWS*DM];
__device__ __half g_hnh [(size_t)NROWS*DM];
__device__ __half g_ffh [(size_t)NROWS*DFF];
// fp16 weight copies
__device__ __half g_wqkv[(size_t)3*DM*DM];
__device__ float  g_bqkv[QL];
__device__ __half g_wo[(size_t)DM*DM];
__device__ __half g_w1[(size_t)DFF*DM];
__device__ __half g_w2[(size_t)DM*DFF];
__device__ __half g_pj[(size_t)MFEAT*HD];

// ===================== helpers =====================
static __device__ __forceinline__ uint32_t smem_u32(const void* p) {
    uint32_t a;
    asm("{ .reg .u64 t; cvta.to.shared.u64 t, %1; cvt.u32.u64 %0, t; }"
        : "=r"(a) : "l"(p));
    return a;
}
static __device__ __forceinline__ void cp16(uint32_t dst, const void* src, int sz) {
    asm volatile("cp.async.cg.shared.global [%0], [%1], 16, %2;"
                 :: "r"(dst), "l"(src), "r"(sz));
}
#define CP_COMMIT() asm volatile("cp.async.commit_group;" ::: "memory")
#define CP_WAIT1()  asm volatile("cp.async.wait_group 1;" ::: "memory")

static __device__ __forceinline__ void mma16(float* c, const uint32_t* a, const uint32_t* b) {
    asm volatile(
        "mma.sync.aligned.m16n8k16.row.col.f32.f16.f16.f32 "
        "{%0,%1,%2,%3}, {%4,%5,%6,%7}, {%8,%9}, {%0,%1,%2,%3};"
        : "+f"(c[0]), "+f"(c[1]), "+f"(c[2]), "+f"(c[3])
        : "r"(a[0]), "r"(a[1]), "r"(a[2]), "r"(a[3]), "r"(b[0]), "r"(b[1]));
}
static __device__ __forceinline__ void ldsm4t(uint32_t* r, uint32_t addr) {
    asm volatile("ldmatrix.sync.aligned.m8n8.x4.trans.shared.b16 {%0,%1,%2,%3}, [%4];"
        : "=r"(r[0]), "=r"(r[1]), "=r"(r[2]), "=r"(r[3]) : "r"(addr));
}
static __device__ __forceinline__ void store2(__half* p, float x, float y) {
    *(__half2*)p = __floats2half2_rn(x, y);
}
static __device__ __forceinline__ void store2(float* p, float x, float y) {
    *(float2*)p = make_float2(x, y);
}
static __device__ __forceinline__ unsigned encf(float f) {
    unsigned u = __float_as_uint(f);
    return (u & 0x80000000u) ? ~u : (u | 0x80000000u);
}
static __device__ __forceinline__ float decf(unsigned u) {
    u = (u & 0x80000000u) ? (u ^ 0x80000000u) : ~u;
    return __uint_as_float(u);
}

// ===================== v1: fp16 mma NT GEMM, 128x128 tile ==========
// Superstage pipeline: each stage covers K=64 (two 32-K sub-stages), one
// commit group per stage, 2 stages double-buffered. Order per iteration:
//   wait<=1 -> sync -> COMPUTE stage (p&1) -> sync -> prefetch (p+2) -> commit
// MODE 0: plain store. MODE 1: + per-row CTA max. MODE 2: fused divide.
#define HSUB 4096                  // u32 per 32-K sub-stage (A 2048 + B 2048)
#define HSS  (2*HSUB)              // u32 per superstage
#define HSM  (2*HSS*4)             // 64KB

template<int MODE, typename CT>
__global__ __launch_bounds__(256)
void hgemm(const __half* __restrict__ A, const __half* __restrict__ B,
           CT* __restrict__ C, float* __restrict__ pmax, int NX,
           int M, int N, int K, int lda, int ldb, int ldc,
           long long sAo, long long sAi, long long sBo, long long sBi,
           long long sCo, long long sCi, int zdiv)
{
    extern __shared__ uint32_t smem[];
    const int tid = threadIdx.x, lane = tid & 31, w = tid >> 5;
    const int wm = w & 1, wn = w >> 1;
    const uint32_t sbase = smem_u32(smem);

    const int z = blockIdx.z;
    const int zo = z / zdiv, zi = z - zo * zdiv;
    const __half* Ag = A + (size_t)zo * sAo + (size_t)zi * sAi;
    const __half* Bg = B + (size_t)zo * sBo + (size_t)zi * sBi;
    CT* Cg = C + (size_t)zo * sCo + (size_t)zi * sCi;
    const int m0 = blockIdx.y * 128, n0 = blockIdx.x * 128;

    const __half* asrc[2]; uint32_t adst[2];
    const __half* bsrc[2]; uint32_t bdst[2]; int bsz[2];
    #pragma unroll
    for (int j = 0; j < 2; j++) {
        int c = j * 256 + tid;
        int row = c >> 2, o = c & 3;
        {
            int reg = ((row >> 3) & 1) + ((o & 1) << 1);
            int idx = (((o >> 1) * 8 + (row >> 4)) * 4 + reg) * 32 + (row & 7) * 4;
            adst[j] = sbase + idx * 4;
            asrc[j] = Ag + (size_t)(m0 + row) * lda + o * 8;
        }
        {
            int reg = o & 1;
            int idx = 2048 + (((o >> 1) * 16 + (row >> 3)) * 2 + reg) * 32 + (row & 7) * 4;
            bdst[j] = sbase + idx * 4;
            int rr = (n0 + row) < N ? (n0 + row) : 0;
            bsrc[j] = Bg + (size_t)rr * ldb + o * 8;
            bsz[j] = (n0 + row) < N ? 16 : 0;
        }
    }

    float acc[4][4][4];
    #pragma unroll
    for (int a = 0; a < 4; a++)
        #pragma unroll
        for (int b = 0; b < 4; b++)
            #pragma unroll
            for (int c = 0; c < 4; c++) acc[a][b][c] = 0.f;

    const int npair = (K >> 5) >> 1;   // K/64 superstages (K/32 always even here)
    #pragma unroll
    for (int s = 0; s < 2; s++) {
        if (s < npair) {
            #pragma unroll
            for (int sub = 0; sub < 2; sub++) {
                uint32_t so = (uint32_t)s * (HSS * 4) + (uint32_t)sub * (HSUB * 4);
                int koff = (s * 2 + sub) * 32;
                #pragma unroll
                for (int j = 0; j < 2; j++) {
                    cp16(adst[j] + so, asrc[j] + koff, 16);
                    cp16(bdst[j] + so, bsrc[j] + koff, bsz[j]);
                }
            }
        }
        CP_COMMIT();
    }

    for (int p = 0; p < npair; p++) {
        CP_WAIT1();
        __syncthreads();
        // compute both 32-K sub-stages of superstage (p & 1)
        const uint32_t* ss = smem + (size_t)(p & 1) * HSS;
        #pragma unroll
        for (int sub = 0; sub < 2; sub++) {
            const uint32_t* sa = ss + (size_t)sub * HSUB;
            const uint32_t* sb = sa + 2048;
            #pragma unroll
            for (int kb = 0; kb < 2; kb++) {
                uint32_t af[4][4], bf[4][2];
                #pragma unroll
                for (int mt = 0; mt < 4; mt++) {
                    const uint32_t* pp = sa + (size_t)((kb * 8 + wm * 4 + mt) * 4) * 32 + lane;
                    af[mt][0] = pp[0]; af[mt][1] = pp[32]; af[mt][2] = pp[64]; af[mt][3] = pp[96];
                }
                #pragma unroll
                for (int nt = 0; nt < 4; nt++) {
                    const uint32_t* pp = sb + (size_t)((kb * 16 + wn * 4 + nt) * 2) * 32 + lane;
                    bf[nt][0] = pp[0]; bf[nt][1] = pp[32];
                }
                #pragma unroll
                for (int mt = 0; mt < 4; mt++)
                    #pragma unroll
                    for (int nt = 0; nt < 4; nt++)
                        mma16(acc[mt][nt], af[mt], bf[nt]);
            }
        }
        // all warps done reading stage (p&1) before it is refilled
        __syncthreads();
        if (p + 2 < npair) {
            uint32_t so0 = (uint32_t)(p & 1) * (HSS * 4);
            #pragma unroll
            for (int sub = 0; sub < 2; sub++) {
                uint32_t so = so0 + (uint32_t)sub * (HSUB * 4);
                int koff = ((p + 2) * 2 + sub) * 32;
                #pragma unroll
                for (int j = 0; j < 2; j++) {
                    cp16(adst[j] + so, asrc[j] + koff, 16);
                    cp16(bdst[j] + so, bsrc[j] + koff, bsz[j]);
                }
            }
        }
        CP_COMMIT();
    }

    if (MODE == 2) {
        __shared__ float den[128];
        __syncthreads();
        if (wn == 2 && (lane & 3) == 0) {
            #pragma unroll
            for (int mt = 0; mt < 4; mt++) {
                int rl = wm * 64 + mt * 16 + (lane >> 2);
                den[rl] = acc[mt][0][0] + 1e-6f;
                den[rl + 8] = acc[mt][0][2] + 1e-6f;
            }
        }
        __syncthreads();
        if (wn < 2) {
            #pragma unroll
            for (int mt = 0; mt < 4; mt++) {
                int rl = wm * 64 + mt * 16 + (lane >> 2);
                float d0 = den[rl], d1 = den[rl + 8];
                #pragma unroll
                for (int nt = 0; nt < 4; nt++) {
                    int c0 = wn * 32 + nt * 8 + (lane & 3) * 2;
                    __half* p0 = (__half*)Cg + (size_t)(m0 + rl) * ldc + c0;
                    __half* p1 = (__half*)Cg + (size_t)(m0 + rl + 8) * ldc + c0;
                    store2(p0, acc[mt][nt][0] / d0, acc[mt][nt][1] / d0);
                    store2(p1, acc[mt][nt][2] / d1, acc[mt][nt][3] / d1);
                }
            }
        }
        return;
    }

    #pragma unroll
    for (int mt = 0; mt < 4; mt++) {
        const int r0 = m0 + wm * 64 + mt * 16 + (lane >> 2);
        #pragma unroll
        for (int nt = 0; nt < 4; nt++) {
            const int c0 = n0 + wn * 32 + nt * 8 + (lane & 3) * 2;
            if (c0 < N) {
                store2(Cg + (size_t)r0 * ldc + c0, acc[mt][nt][0], acc[mt][nt][1]);
                store2(Cg + (size_t)(r0 + 8) * ldc + c0, acc[mt][nt][2], acc[mt][nt][3]);
            }
        }
    }

    if (MODE == 1) {
        __shared__ unsigned smax[128];
        __syncthreads();
        if (tid < 128) smax[tid] = 0u;
        __syncthreads();
        #pragma unroll
        for (int mt = 0; mt < 4; mt++) {
            float v0 = -1e30f, v1 = -1e30f;
            #pragma unroll
            for (int nt = 0; nt < 4; nt++) {
                int c0 = n0 + wn * 32 + nt * 8 + (lane & 3) * 2;
                if (c0 < N) {
                    v0 = fmaxf(v0, fmaxf(acc[mt][nt][0], acc[mt][nt][1]));
                    v1 = fmaxf(v1, fmaxf(acc[mt][nt][2], acc[mt][nt][3]));
                }
            }
            v0 = fmaxf(v0, __shfl_xor_sync(~0u, v0, 1));
            v0 = fmaxf(v0, __shfl_xor_sync(~0u, v0, 2));
            v1 = fmaxf(v1, __shfl_xor_sync(~0u, v1, 1));
            v1 = fmaxf(v1, __shfl_xor_sync(~0u, v1, 2));
            if ((lane & 3) == 0) {
                int rl = wm * 64 + mt * 16 + (lane >> 2);
                atomicMax(&smax[rl], encf(v0));
                atomicMax(&smax[rl + 8], encf(v1));
            }
        }
        __syncthreads();
        if (tid < 128)
            pmax[((size_t)z * NX + blockIdx.x) * M + m0 + tid] = decf(smax[tid]);
    }
}

// ===================== v2: 128x256 tile, superstage (K=64) pipeline ==========
#define H2SUB 6144                 // u32 per 32-K sub-stage (A 2048 + B 4096)
#define H2SS  (2*H2SUB)
#define H2SM  (2*H2SS*4)           // 96KB

template<bool RELU, bool RES, bool BIAS, typename CT>
__global__ __launch_bounds__(256)
void hgemm2(const __half* __restrict__ A, const __half* __restrict__ B,
            const float* __restrict__ bias, const float* __restrict__ res,
            CT* __restrict__ C, int M, int N, int K, int lda, int ldb, int ldc)
{
    extern __shared__ uint32_t smem[];
    const int tid = threadIdx.x, lane = tid & 31, w = tid >> 5;
    const int wm = w & 1, wn = w >> 1;
    const uint32_t sbase = smem_u32(smem);
    const int m0 = blockIdx.y * 128, n0 = blockIdx.x * 256;

    const __half* asrc[2]; uint32_t adst[2];
    #pragma unroll
    for (int j = 0; j < 2; j++) {
        int c = j * 256 + tid;
        int row = c >> 2, o = c & 3;
        int reg = ((row >> 3) & 1) + ((o & 1) << 1);
        int idx = (((o >> 1) * 8 + (row >> 4)) * 4 + reg) * 32 + (row & 7) * 4;
        adst[j] = sbase + idx * 4;
        asrc[j] = A + (size_t)(m0 + row) * lda + o * 8;
    }
    const __half* bsrc[4]; uint32_t bdst[4];
    #pragma unroll
    for (int j = 0; j < 4; j++) {
        int c = j * 256 + tid;
        int row = c >> 2, o = c & 3;
        int reg = o & 1;
        int idx = 2048 + (((o >> 1) * 32 + (row >> 3)) * 2 + reg) * 32 + (row & 7) * 4;
        bdst[j] = sbase + idx * 4;
        bsrc[j] = B + (size_t)(n0 + row) * ldb + o * 8;
    }

    float acc[4][8][4];
    #pragma unroll
    for (int a = 0; a < 4; a++)
        #pragma unroll
        for (int b = 0; b < 8; b++)
            #pragma unroll
            for (int c = 0; c < 4; c++) acc[a][b][c] = 0.f;

    const int npair = (K >> 5) >> 1;
    #pragma unroll
    for (int s = 0; s < 2; s++) {
        if (s < npair) {
            #pragma unroll
            for (int sub = 0; sub < 2; sub++) {
                uint32_t so = (uint32_t)s * (H2SS * 4) + (uint32_t)sub * (H2SUB * 4);
                int koff = (s * 2 + sub) * 32;
                #pragma unroll
                for (int j = 0; j < 2; j++) cp16(adst[j] + so, asrc[j] + koff, 16);
                #pragma unroll
                for (int j = 0; j < 4; j++) cp16(bdst[j] + so, bsrc[j] + koff, 16);
            }
        }
        CP_COMMIT();
    }

    for (int p = 0; p < npair; p++) {
        CP_WAIT1();
        __syncthreads();
        const uint32_t* ss = smem + (size_t)(p & 1) * H2SS;
        #pragma unroll
        for (int sub = 0; sub < 2; sub++) {
            const uint32_t* sa = ss + (size_t)sub * H2SUB;
            const uint32_t* sb = sa + 2048;
            #pragma unroll
            for (int kb = 0; kb < 2; kb++) {
                uint32_t af[4][4], bf[8][2];
                #pragma unroll
                for (int mt = 0; mt < 4; mt++) {
                    const uint32_t* pp = sa + (size_t)((kb * 8 + wm * 4 + mt) * 4) * 32 + lane;
                    af[mt][0] = pp[0]; af[mt][1] = pp[32]; af[mt][2] = pp[64]; af[mt][3] = pp[96];
                }
                #pragma unroll
                for (int nt = 0; nt < 8; nt++) {
                    const uint32_t* pp = sb + (size_t)((kb * 32 + wn * 8 + nt) * 2) * 32 + lane;
                    bf[nt][0] = pp[0]; bf[nt][1] = pp[32];
                }
                #pragma unroll
                for (int mt = 0; mt < 4; mt++)
                    #pragma unroll
                    for (int nt = 0; nt < 8; nt++)
                        mma16(acc[mt][nt], af[mt], bf[nt]);
            }
        }
        __syncthreads();
        if (p + 2 < npair) {
            uint32_t so0 = (uint32_t)(p & 1) * (H2SS * 4);
            #pragma unroll
            for (int sub = 0; sub < 2; sub++) {
                uint32_t so = so0 + (uint32_t)sub * (H2SUB * 4);
                int koff = ((p + 2) * 2 + sub) * 32;
                #pragma unroll
                for (int j = 0; j < 2; j++) cp16(adst[j] + so, asrc[j] + koff, 16);
                #pragma unroll
                for (int j = 0; j < 4; j++) cp16(bdst[j] + so, bsrc[j] + koff, 16);
            }
        }
        CP_COMMIT();
    }

    #pragma unroll
    for (int mt = 0; mt < 4; mt++) {
        const int r0 = m0 + wm * 64 + mt * 16 + (lane >> 2);
        #pragma unroll
        for (int nt = 0; nt < 8; nt++) {
            const int c0 = n0 + wn * 64 + nt * 8 + (lane & 3) * 2;
            float bx = 0.f, by = 0.f;
            if (BIAS) { float2 b2 = *(const float2*)(bias + c0); bx = b2.x; by = b2.y; }
            float x0 = acc[mt][nt][0] + bx, x1 = acc[mt][nt][1] + by;
            float y0 = acc[mt][nt][2] + bx, y1 = acc[mt][nt][3] + by;
            if (RES) {
                float2 ra = *(const float2*)(res + (size_t)r0 * ldc + c0);
                float2 rb = *(const float2*)(res + (size_t)(r0 + 8) * ldc + c0);
                x0 += ra.x; x1 += ra.y; y0 += rb.x; y1 += rb.y;
            }
            if (RELU) {
                x0 = fmaxf(x0, 0.f); x1 = fmaxf(x1, 0.f);
                y0 = fmaxf(y0, 0.f); y1 = fmaxf(y1, 0.f);
            }
            store2(C + (size_t)r0 * ldc + c0, x0, x1);
            store2(C + (size_t)(r0 + 8) * ldc + c0, y0, y1);
        }
    }
}

// ===================== fp16 TN GEMM for kvs, writes kvsT transposed ==========
#define TNSTG 3072
#define TNSM (2*TNSTG*4)

__global__ __launch_bounds__(256)
void kvs_gemm(const __half* __restrict__ kp, const __half* __restrict__ v,
              __half* __restrict__ kvsT)
{
    extern __shared__ uint32_t smem[];
    const int tid = threadIdx.x, lane = tid & 31, w = tid >> 5;
    const int wm = w >> 2, wn = w & 3;
    const uint32_t sbase = smem_u32(smem);
    const int bh = blockIdx.z, b = bh >> 4, h = bh & 15;
    const int m0 = blockIdx.x * 128;
    const __half* Ag = kp + (size_t)bh * SEQ * MP;
    const __half* Bg = v + (size_t)b * SEQ * QL + h * HD;

    const __half* asrc[2]; uint32_t adst[2]; int asz[2];
    #pragma unroll
    for (int j = 0; j < 2; j++) {
        int c = j * 256 + tid;
        int row = c >> 4, u = c & 15;
        adst[j] = sbase + row * 256 + ((u ^ (row & 7)) << 4);
        bool val = (m0 + u * 8) < MP;
        asrc[j] = Ag + (size_t)row * MP + (val ? (m0 + u * 8) : 0);
        asz[j] = val ? 16 : 0;
    }
    const int brow = tid >> 3, bu = tid & 7;
    const uint32_t bdst = sbase + 8192 + brow * 128 + ((bu ^ (brow & 7)) << 4);
    const __half* bsrc = Bg + (size_t)brow * QL + bu * 8;

    float acc[4][2][4];
    #pragma unroll
    for (int a = 0; a < 4; a++)
        #pragma unroll
        for (int bb = 0; bb < 2; bb++)
            #pragma unroll
            for (int c = 0; c < 4; c++) acc[a][bb][c] = 0.f;

    const int nk = SEQ / 32;
    #pragma unroll
    for (int j = 0; j < 2; j++) cp16(adst[j], asrc[j], asz[j]);
    cp16(bdst, bsrc, 16);
    CP_COMMIT();

    const int q = lane >> 3, r = lane & 7;
    for (int i = 0; i < nk; i++) {
        if (i + 1 < nk) {
            uint32_t so = (uint32_t)((i + 1) & 1) * (TNSTG * 4);
            size_t ko = (size_t)(i + 1) * 32;
            #pragma unroll
            for (int j = 0; j < 2; j++) cp16(adst[j] + so, asrc[j] + ko * MP, asz[j]);
            cp16(bdst + so, bsrc + ko * QL, 16);
        }
        CP_COMMIT();
        CP_WAIT1();
        __syncthreads();
        const uint32_t st = sbase + (uint32_t)(i & 1) * (TNSTG * 4);
        #pragma unroll
        for (int kb = 0; kb < 2; kb++) {
            uint32_t bf[4];
            {
                int krow = kb * 16 + (q & 1) * 8 + r;
                int du = wn * 2 + (q >> 1);
                ldsm4t(bf, st + 8192 + krow * 128 + ((du ^ (krow & 7)) << 4));
            }
            #pragma unroll
            for (int mt = 0; mt < 4; mt++) {
                uint32_t af[4];
                int krow = kb * 16 + (q >> 1) * 8 + r;
                int mu = wm * 8 + mt * 2 + (q & 1);
                ldsm4t(af, st + krow * 256 + ((mu ^ (krow & 7)) << 4));
                mma16(acc[mt][0], af, bf);
                mma16(acc[mt][1], af, bf + 2);
            }
        }
        __syncthreads();
    }

    __half* outp = kvsT + (size_t)bh * KVR * MP;
    #pragma unroll
    for (int mt = 0; mt < 4; mt++) {
        const int r0 = m0 + wm * 64 + mt * 16 + (lane >> 2);
        #pragma unroll
        for (int nt = 0; nt < 2; nt++) {
            const int c0 = wn * 16 + nt * 8 + (lane & 3) * 2;
            if (r0 < MP) {
                outp[(size_t)c0 * MP + r0]       = __float2half(acc[mt][nt][0]);
                outp[(size_t)(c0 + 1) * MP + r0] = __float2half(acc[mt][nt][1]);
            }
            if (r0 + 8 < MP) {
                outp[(size_t)c0 * MP + r0 + 8]       = __float2half(acc[mt][nt][2]);
                outp[(size_t)(c0 + 1) * MP + r0 + 8] = __float2half(acc[mt][nt][3]);
            }
        }
    }
}

// ----------------- fp32 -> fp16 converts -----------------
__global__ void cvt_kernel(const float* __restrict__ s, __half* __restrict__ d, int n4)
{
    int i = blockIdx.x * 256 + threadIdx.x;
    if (i >= n4) return;
    float4 v = ((const float4*)s)[i];
    __half2* o = (__half2*)d + (size_t)i * 2;
    o[0] = __floats2half2_rn(v.x, v.y);
    o[1] = __floats2half2_rn(v.z, v.w);
}

__global__ void cvt3_kernel(const float* __restrict__ s0, const float* __restrict__ s1,
                            const float* __restrict__ s2, __half* __restrict__ d)
{
    const int n4 = DM * DM / 4;
    int i = blockIdx.x * 256 + threadIdx.x;
    if (i >= 3 * n4) return;
    int seg = i / n4, off = i - seg * n4;
    const float* s = (seg == 0) ? s0 : (seg == 1) ? s1 : s2;
    float4 v = ((const float4*)s)[off];
    __half2* o = (__half2*)d + (size_t)i * 2;
    o[0] = __floats2half2_rn(v.x, v.y);
    o[1] = __floats2half2_rn(v.z, v.w);
}

// ----------------- bias concat (fp32) -----------------
__global__ void biascat_kernel(const float* __restrict__ qb, const float* __restrict__ kb,
                               const float* __restrict__ vb, float* __restrict__ o)
{
    int i = blockIdx.x * 256 + threadIdx.x;
    if (i >= QL) return;
    int seg = i >> 10, off = i & 1023;
    o[i] = (seg == 0) ? qb[off] : (seg == 1) ? kb[off] : vb[off];
}

// ----------------- LayerNorm (fp32 in, fp16 out) -----------------
__global__ __launch_bounds__(256)
void ln_kernel(const float* __restrict__ x, const float* __restrict__ g,
               const float* __restrict__ beta, __half* __restrict__ y)
{
    size_t row = blockIdx.x;
    int tid = threadIdx.x;
    float4 v = ((const float4*)(x + row * DM))[tid];
    float s = v.x + v.y + v.z + v.w;
    __shared__ float sm[8];
    #pragma unroll
    for (int o = 16; o > 0; o >>= 1) s += __shfl_xor_sync(~0u, s, o);
    if ((tid & 31) == 0) sm[tid >> 5] = s;
    __syncthreads();
    float mu = 0.f;
    #pragma unroll
    for (int i = 0; i < 8; i++) mu += sm[i];
    mu *= (1.f / (float)DM);
    float dx = v.x - mu, dy = v.y - mu, dz = v.z - mu, dw = v.w - mu;
    float q = dx*dx + dy*dy + dz*dz + dw*dw;
    __syncthreads();
    #pragma unroll
    for (int o = 16; o > 0; o >>= 1) q += __shfl_xor_sync(~0u, q, o);
    if ((tid & 31) == 0) sm[tid >> 5] = q;
    __syncthreads();
    float var = 0.f;
    #pragma unroll
    for (int i = 0; i < 8; i++) var += sm[i];
    var *= (1.f / (float)DM);
    float inv = rsqrtf(var + 1e-5f);
    float4 gg = ((const float4*)g)[tid];
    float4 bb = ((const float4*)beta)[tid];
    __half2* o = (__half2*)(y + row * DM) + tid * 2;
    o[0] = __floats2half2_rn(dx * inv * gg.x + bb.x, dy * inv * gg.y + bb.y);
    o[1] = __floats2half2_rn(dz * inv * gg.z + bb.z, dw * inv * gg.w + bb.w);
}

// ----------------- kstab -----------------
__global__ void kstab_kernel(const float* __restrict__ pmaxk, float* __restrict__ stab)
{
    int i = blockIdx.x * 256 + threadIdx.x;
    if (i >= BATCHN * SEQ) return;
    int b = i >> 11, l = i & (SEQ - 1);
    float mx = -1e30f;
    #pragma unroll
    for (int h = 0; h < NH; h++)
        #pragma unroll
        for (int x = 0; x < NXT; x++)
            mx = fmaxf(mx, pmaxk[((size_t)(b * NH + h) * NXT + x) * SEQ + l]);
    stab[i] = mx;
}

// ----------------- q exp (in-place on fp16 qp) -----------------
__global__ __launch_bounds__(256)
void qexp_kernel(__half* __restrict__ qp, const __half* __restrict__ qkv,
                 const float* __restrict__ pmaxq)
{
    const int rr = blockIdx.x * 8 + (threadIdx.x >> 5);
    const int lane = threadIdx.x & 31;
    const int bh = rr >> 11, l = rr & (SEQ - 1);
    const int b = bh >> 4, h = bh & 15;
    float mx = -1e30f;
    #pragma unroll
    for (int x = 0; x < NXT; x++)
        mx = fmaxf(mx, pmaxq[((size_t)bh * NXT + x) * SEQ + l]);
    mx *= DN;
    const __half* qr = qkv + ((size_t)(b * SEQ + l)) * QL + h * HD;
    float a = __half2float(qr[lane]), bb2 = __half2float(qr[lane + 32]);
    float s = a * a + bb2 * bb2;
    #pragma unroll
    for (int o = 16; o > 0; o >>= 1) s += __shfl_xor_sync(~0u, s, o);
    const float dia = 0.5f * DN * DN * s;
    __half* row = qp + (size_t)rr * MP;
    #pragma unroll
    for (int j = 0; j < 18; j++) {
        int m = j * 32 + lane;
        if (m < MP) {
            float v = (m < MFEAT)
                ? RATIO * (__expf(DN * __half2float(row[m]) - mx - dia) + FEPS) : 0.f;
            row[m] = __float2half(v);
        }
    }
}

// ----------------- k exp (in-place on fp16 kp) -----------------
__global__ __launch_bounds__(256)
void kexp_kernel(__half* __restrict__ kp, const __half* __restrict__ qkv,
                 const float* __restrict__ stab, const unsigned char* __restrict__ padmask)
{
    const int rr = blockIdx.x * 8 + (threadIdx.x >> 5);
    const int lane = threadIdx.x & 31;
    const int bh = rr >> 11, l = rr & (SEQ - 1);
    const int b = bh >> 4, h = bh & 15;
    const float mx = DN * stab[b * SEQ + l];
    const __half* kr = qkv + ((size_t)(b * SEQ + l)) * QL + DM + h * HD;
    float a = __half2float(kr[lane]), bb2 = __half2float(kr[lane + 32]);
    float s = a * a + bb2 * bb2;
    #pragma unroll
    for (int o = 16; o > 0; o >>= 1) s += __shfl_xor_sync(~0u, s, o);
    const float dia = 0.5f * DN * DN * s;
    const float keep = padmask[b * SEQ + l] ? 0.f : 1.f;
    __half* row = kp + (size_t)rr * MP;
    #pragma unroll
    for (int j = 0; j < 18; j++) {
        int m = j * 32 + lane;
        if (m < MP) {
            float v = (m < MFEAT)
                ? keep * RATIO * (__expf(DN * __half2float(row[m]) - mx - dia) + FEPS) : 0.f;
            row[m] = __float2half(v);
        }
    }
}

// ks_sum (row 64) + zero rows 65..127
__global__ void kssum_kernel(const __half* __restrict__ kp, __half* __restrict__ kvsT)
{
    int bh = blockIdx.y;
    int m = blockIdx.x * 192 + threadIdx.x;
    if (m >= MP) return;
    const __half* p = kp + (size_t)bh * SEQ * MP + m;
    float a0 = 0.f, a1 = 0.f, a2 = 0.f, a3 = 0.f;
    for (int l = 0; l < SEQ; l += 4) {
        a0 += __half2float(p[(size_t)l * MP]);
        a1 += __half2float(p[(size_t)(l + 1) * MP]);
        a2 += __half2float(p[(size_t)(l + 2) * MP]);
        a3 += __half2float(p[(size_t)(l + 3) * MP]);
    }
    __half* o = kvsT + (size_t)bh * KVR * MP;
    o[(size_t)64 * MP + m] = __float2half((a0 + a1) + (a2 + a3));
    for (int r = 65; r < KVR; r++) o[(size_t)r * MP + m] = __float2half(0.f);
}

// ----------------- launch -----------------
static void* getsym(const void* shadow)
{
    void* p = nullptr;
    cudaGetSymbolAddress(&p, shadow);
    return p;
}

extern "C" void kernel_launch(void* const* d_in, const int* in_sizes, int n_in,
                              void* d_out, int out_size)
{
    const float* src    = (const float*)d_in[0];
    const unsigned char* mask = (const unsigned char*)d_in[1];
    const float* proj   = (const float*)d_in[2];
    const float* q_w    = (const float*)d_in[3];
    const float* q_b    = (const float*)d_in[4];
    const float* k_w    = (const float*)d_in[5];
    const float* k_b    = (const float*)d_in[6];
    const float* v_w    = (const float*)d_in[7];
    const float* v_b    = (const float*)d_in[8];
    const float* out_w  = (const float*)d_in[9];
    const float* out_b  = (const float*)d_in[10];
    const float* ln1_g  = (const float*)d_in[11];
    const float* ln1_b  = (const float*)d_in[12];
    const float* ln2_g  = (const float*)d_in[13];
    const float* ln2_b  = (const float*)d_in[14];
    const float* ff1_w  = (const float*)d_in[15];
    const float* ff1_b  = (const float*)d_in[16];
    const float* ff2_w  = (const float*)d_in[17];
    const float* ff2_b  = (const float*)d_in[18];
    float* out = (float*)d_out;

    __half* p_xn   = (__half*)getsym(g_xnh);
    __half* p_qkv  = (__half*)getsym(g_qkvh);
    __half* p_qp   = (__half*)getsym(g_qph);
    __half* p_kp   = (__half*)getsym(g_kph);
    float*  p_pmq  = (float*)getsym(g_pmaxq);
    float*  p_pmk  = (float*)getsym(g_pmaxk);
    float*  p_stab = (float*)getsym(g_stab);
    __half* p_kvsT = (__half*)getsym(g_kvsTh);
    __half* p_attn = (__half*)getsym(g_attnh);
    float*  p_x1   = (float*)getsym(g_x1);
    __half* p_hn   = (__half*)getsym(g_hnh);
    __half* p_ff   = (__half*)getsym(g_ffh);
    __half* p_wqkv = (__half*)getsym(g_wqkv);
    float*  p_bqkv = (float*)getsym(g_bqkv);
    __half* p_wo   = (__half*)getsym(g_wo);
    __half* p_w1   = (__half*)getsym(g_w1);
    __half* p_w2   = (__half*)getsym(g_w2);
    __half* p_pj   = (__half*)getsym(g_pj);

    cudaFuncSetAttribute(hgemm<1,__half>,
                         cudaFuncAttributeMaxDynamicSharedMemorySize, HSM);
    cudaFuncSetAttribute(hgemm<2,__half>,
                         cudaFuncAttributeMaxDynamicSharedMemorySize, HSM);
    cudaFuncSetAttribute(hgemm2<false,false,true,__half>,
                         cudaFuncAttributeMaxDynamicSharedMemorySize, H2SM);
    cudaFuncSetAttribute(hgemm2<false,true,true,float>,
                         cudaFuncAttributeMaxDynamicSharedMemorySize, H2SM);
    cudaFuncSetAttribute(hgemm2<true,false,true,__half>,
                         cudaFuncAttributeMaxDynamicSharedMemorySize, H2SM);
    cudaFuncSetAttribute(kvs_gemm,
                         cudaFuncAttributeMaxDynamicSharedMemorySize, TNSM);

    // launches 1-3 (ncu capture slot #4 = QKV GEMM)
    {
        int n4t = 3 * DM * DM / 4;
        cvt3_kernel<<<(n4t + 255) / 256, 256>>>(q_w, k_w, v_w, p_wqkv);
    }
    biascat_kernel<<<(QL + 255) / 256, 256>>>(q_b, k_b, v_b, p_bqkv);
    ln_kernel<<<NROWS, 256>>>(src, ln1_g, ln1_b, p_xn);

    // launch 4: merged QKV GEMM (N=3072)
    hgemm2<false,false,true,__half><<<dim3(QL / 256, NROWS / 128, 1), 256, H2SM>>>(
        p_xn, p_wqkv, p_bqkv, nullptr, p_qkv, NROWS, QL, DM, DM, DM, QL);

    // remaining weight converts
    {
        int n4 = DM * DM / 4;
        cvt_kernel<<<(n4 + 255) / 256, 256>>>(out_w, p_wo, n4);
        int nf = DFF * DM / 4;
        cvt_kernel<<<(nf + 255) / 256, 256>>>(ff1_w, p_w1, nf);
        cvt_kernel<<<(nf + 255) / 256, 256>>>(ff2_w, p_w2, nf);
        int np = MFEAT * HD / 4;
        cvt_kernel<<<(np + 255) / 256, 256>>>(proj, p_pj, np);
    }

    // feature GEMMs (MODE 1) + in-place exp epilogues
    dim3 gF(NXT, SEQ / 128, NBH);
    hgemm<1,__half><<<gF, 256, HSM>>>(
        p_qkv, p_pj, p_qp, p_pmq, NXT, SEQ, MFEAT, HD, QL, HD, MP,
        (long long)SEQ * QL, HD, 0, 0, (long long)NH * SEQ * MP, (long long)SEQ * MP, NH);
    qexp_kernel<<<NBH * SEQ / 8, 256>>>(p_qp, p_qkv, p_pmq);
    hgemm<1,__half><<<gF, 256, HSM>>>(
        p_qkv + DM, p_pj, p_kp, p_pmk, NXT, SEQ, MFEAT, HD, QL, HD, MP,
        (long long)SEQ * QL, HD, 0, 0, (long long)NH * SEQ * MP, (long long)SEQ * MP, NH);
    kstab_kernel<<<(BATCHN * SEQ + 255) / 256, 256>>>(p_pmk, p_stab);
    kexp_kernel<<<NBH * SEQ / 8, 256>>>(p_kp, p_qkv, p_stab, mask);

    // kvs (writes kvsT transposed) + ks_sum/zero-pad
    kvs_gemm<<<dim3((MP + 127) / 128, 1, NBH), 256, TNSM>>>(p_kp, p_qkv + 2 * DM, p_kvsT);
    kssum_kernel<<<dim3(3, NBH), 192>>>(p_kp, p_kvsT);

    // numer GEMM with fused divide -> attn fp16 [b,l,h,d]
    hgemm<2,__half><<<dim3(1, SEQ / 128, NBH), 256, HSM>>>(
        p_qp, p_kvsT, p_attn, nullptr, 1, SEQ, KVR, MP, MP, MP, DM,
        (long long)NH * SEQ * MP, (long long)SEQ * MP,
        (long long)NH * KVR * MP, (long long)KVR * MP,
        (long long)SEQ * DM, HD, NH);

    // out projection + residual(src) -> x1 fp32
    dim3 gO(DM / 256, NROWS / 128, 1);
    hgemm2<false,true,true,float><<<gO, 256, H2SM>>>(
        p_attn, p_wo, out_b, src, p_x1, NROWS, DM, DM, DM, DM, DM);

    // LN2 -> fp16
    ln_kernel<<<NROWS, 256>>>(p_x1, ln2_g, ln2_b, p_hn);

    // FF1 (+ReLU) -> fp16
    hgemm2<true,false,true,__half><<<dim3(DFF / 256, NROWS / 128, 1), 256, H2SM>>>(
        p_hn, p_w1, ff1_b, nullptr, p_ff, NROWS, DFF, DM, DM, DM, DFF);

    // FF2 + residual(x1) -> final fp32 output
    hgemm2<false,true,true,float><<<gO, 256, H2SM>>>(
        p_ff, p_w2, ff2_b, p_x1, out, NROWS, DM, DFF, DFF, DFF, DM);
}